// round 2
// baseline (speedup 1.0000x reference)
#include <cuda_runtime.h>
#include <cstdint>
#include <cfloat>
#include <math.h>

#define Bc 2
#define Tc 1024
#define Dc 1024
#define Hc 16
#define DHc 64
#define Rc 32
#define Lc 2
#define FFc 4096
#define OVc 16384

// ---------------- static device scratch (no allocations allowed) ----------------
__device__ float g_delta[Bc*Tc*Rc];
__device__ float g_cos[Bc*Tc*Rc];
__device__ float g_sin[Bc*Tc*Rc];
__device__ float g_x [Bc*Tc*Dc];
__device__ float g_h [Bc*Tc*Dc];
__device__ float g_q [Bc*Tc*Dc];
__device__ float g_k [Bc*Tc*Dc];
__device__ float g_v [Bc*Tc*Dc];
__device__ float g_o [Bc*Tc*Dc];
__device__ float g_ff[Bc*Tc*FFc];
__device__ float g_sc[(size_t)Bc*Hc*Tc*Tc];   // 128 MB attention scores scratch

// ---------------- block reductions ----------------
__device__ __forceinline__ float blockReduceSum(float v) {
    __shared__ float ws[32];
    int lane = threadIdx.x & 31, w = threadIdx.x >> 5;
    #pragma unroll
    for (int o = 16; o; o >>= 1) v += __shfl_down_sync(0xffffffffu, v, o);
    if (lane == 0) ws[w] = v;
    __syncthreads();
    int nw = blockDim.x >> 5;
    v = (threadIdx.x < nw) ? ws[threadIdx.x] : 0.f;
    if (w == 0) {
        #pragma unroll
        for (int o = 16; o; o >>= 1) v += __shfl_down_sync(0xffffffffu, v, o);
        if (lane == 0) ws[0] = v;
    }
    __syncthreads();
    float r = ws[0];
    __syncthreads();
    return r;
}

__device__ __forceinline__ float blockReduceMax(float v) {
    __shared__ float wm[32];
    int lane = threadIdx.x & 31, w = threadIdx.x >> 5;
    #pragma unroll
    for (int o = 16; o; o >>= 1) v = fmaxf(v, __shfl_down_sync(0xffffffffu, v, o));
    if (lane == 0) wm[w] = v;
    __syncthreads();
    int nw = blockDim.x >> 5;
    v = (threadIdx.x < nw) ? wm[threadIdx.x] : -FLT_MAX;
    if (w == 0) {
        #pragma unroll
        for (int o = 16; o; o >>= 1) v = fmaxf(v, __shfl_down_sync(0xffffffffu, v, o));
        if (lane == 0) wm[0] = v;
    }
    __syncthreads();
    float r = wm[0];
    __syncthreads();
    return r;
}

// ---------------- delta = action_emb[actions] @ lie_w + lie_b ----------------
__global__ void delta_kernel(const int* __restrict__ actions,
                             const float* __restrict__ action_emb,
                             const float* __restrict__ lie_w,
                             const float* __restrict__ lie_b,
                             float* __restrict__ delta) {
    int bt = blockIdx.x;
    __shared__ float emb[Dc];
    __shared__ float part[128];
    int a = actions[bt];
    const float* src = action_emb + (size_t)a * Dc;
    for (int i = threadIdx.x; i < Dc; i += blockDim.x) emb[i] = src[i];
    __syncthreads();
    int r = threadIdx.x & 31;
    int seg = threadIdx.x >> 5;        // 0..3, 256 elems each
    float s = 0.f;
    int d0 = seg * 256;
    #pragma unroll 8
    for (int d = d0; d < d0 + 256; d++) s += emb[d] * lie_w[d * Rc + r];
    part[threadIdx.x] = s;
    __syncthreads();
    if (threadIdx.x < 32) {
        float v = part[threadIdx.x] + part[threadIdx.x + 32] +
                  part[threadIdx.x + 64] + part[threadIdx.x + 96];
        delta[(size_t)bt * Rc + threadIdx.x] = v + lie_b[threadIdx.x];
    }
}

// ---------------- inclusive cumsum of angles over T, then cos/sin ----------------
// Block-diag 2x2 rotations commute within a block: prefix matrix product == angle cumsum.
__global__ void scan_kernel(const float* __restrict__ delta,
                            float* __restrict__ cosT, float* __restrict__ sinT) {
    int b = blockIdx.x / Rc, r = blockIdx.x % Rc;
    __shared__ float buf[2][Tc];
    int t = threadIdx.x;
    buf[0][t] = delta[((size_t)b * Tc + t) * Rc + r];
    __syncthreads();
    int src = 0;
    #pragma unroll
    for (int off = 1; off < Tc; off <<= 1) {
        float nv = buf[src][t];
        if (t >= off) nv += buf[src][t - off];
        buf[1 - src][t] = nv;
        src = 1 - src;
        __syncthreads();
    }
    float th = buf[src][t];
    size_t idx = ((size_t)b * Tc + t) * Rc + r;
    cosT[idx] = cosf(th);
    sinT[idx] = sinf(th);
}

// ---------------- x = obs_emb[observations] ----------------
__global__ void gather_kernel(const int* __restrict__ obs,
                              const float* __restrict__ emb,
                              float* __restrict__ x) {
    int bt = blockIdx.x;
    int o = obs[bt];
    const float4* s = (const float4*)(emb + (size_t)o * Dc);
    float4* d = (float4*)(x + (size_t)bt * Dc);
    d[threadIdx.x] = s[threadIdx.x];   // 256 threads * 4 = 1024
}

// ---------------- layernorm (two-pass, population variance, eps 1e-5) ----------------
__global__ void ln_kernel(const float* __restrict__ x,
                          const float* __restrict__ g,
                          const float* __restrict__ b,
                          float* __restrict__ out) {
    int row = blockIdx.x;
    const float4* xr = (const float4*)(x + (size_t)row * Dc);
    float4 v = xr[threadIdx.x];
    float s = v.x + v.y + v.z + v.w;
    s = blockReduceSum(s);
    float mean = s * (1.f / Dc);
    float dx = v.x - mean, dy = v.y - mean, dz = v.z - mean, dw = v.w - mean;
    float s2 = dx*dx + dy*dy + dz*dz + dw*dw;
    s2 = blockReduceSum(s2);
    float rstd = rsqrtf(s2 * (1.f / Dc) + 1e-5f);
    int c = threadIdx.x * 4;
    float4 gv = ((const float4*)g)[threadIdx.x];
    float4 bv = ((const float4*)b)[threadIdx.x];
    float4 o;
    o.x = dx * rstd * gv.x + bv.x;
    o.y = dy * rstd * gv.y + bv.y;
    o.z = dz * rstd * gv.z + bv.z;
    o.w = dw * rstd * gv.w + bv.w;
    ((float4*)(out + (size_t)row * Dc))[threadIdx.x] = o;
    (void)c;
}

// ---------------- apply cumulative rotation to Q and K in-place ----------------
__global__ void rope_kernel(const float* __restrict__ cosT,
                            const float* __restrict__ sinT,
                            float* __restrict__ Q, float* __restrict__ K) {
    int idx = blockIdx.x * blockDim.x + threadIdx.x;   // B*T*H*R
    if (idx >= Bc * Tc * Hc * Rc) return;
    int r = idx & 31;
    int h = (idx >> 5) & 15;
    int bt = idx >> 9;
    float c = cosT[(size_t)bt * Rc + r];
    float s = sinT[(size_t)bt * Rc + r];
    size_t base = (size_t)bt * Dc + h * DHc + 2 * r;
    float2 q = *(float2*)(Q + base);
    float2 k = *(float2*)(K + base);
    float2 qo, ko;
    qo.x = c * q.x - s * q.y;  qo.y = s * q.x + c * q.y;
    ko.x = c * k.x - s * k.y;  ko.y = s * k.x + c * k.y;
    *(float2*)(Q + base) = qo;
    *(float2*)(K + base) = ko;
}

// ---------------- causal softmax over scores rows (scale 1/8 fused) ----------------
__global__ void softmax_kernel(float* __restrict__ scores) {
    int row = blockIdx.x;              // B*H*T rows
    int t = row & (Tc - 1);
    float* p = scores + (size_t)row * Tc;
    int valid = t + 1;
    float4 v = ((float4*)p)[threadIdx.x];
    int base = threadIdx.x * 4;
    float vals[4] = {v.x, v.y, v.z, v.w};
    float m = -FLT_MAX;
    #pragma unroll
    for (int c = 0; c < 4; c++) {
        vals[c] = (base + c < valid) ? vals[c] * 0.125f : -FLT_MAX;
        m = fmaxf(m, vals[c]);
    }
    m = blockReduceMax(m);
    float s = 0.f;
    #pragma unroll
    for (int c = 0; c < 4; c++) {
        vals[c] = (base + c < valid) ? __expf(vals[c] - m) : 0.f;
        s += vals[c];
    }
    s = blockReduceSum(s);
    float inv = 1.f / s;
    float4 o = {vals[0]*inv, vals[1]*inv, vals[2]*inv, vals[3]*inv};
    ((float4*)p)[threadIdx.x] = o;
}

// ---------------- generic SGEMM: 128x128x8 tiles, 8x8 microtiles ----------------
// MODE 0: C = A*B + bias  | MODE 1: + residual | MODE 2: gelu(A*B + bias)
// TRANSB: B given as [N x K] row-major (C = A * B^T)
// batched via blockIdx.z, decomposed into (zb, zh) with per-axis strides.
template<int MODE, bool TRANSB>
__global__ void __launch_bounds__(256)
gemm_kernel(const float* __restrict__ A, const float* __restrict__ Bm,
            const float* __restrict__ bias, const float* __restrict__ Res,
            float* __restrict__ C,
            int M, int N, int K, int lda, int ldb, int ldc,
            int H2, long long sAb, long long sAh, long long sBb, long long sBh,
            long long sCb, long long sCh)
{
    int z = blockIdx.z;
    int zb = z / H2, zh = z % H2;
    A  += zb * sAb + zh * sAh;
    Bm += zb * sBb + zh * sBh;
    C  += zb * sCb + zh * sCh;
    const float* R0 = (MODE == 1) ? (Res + zb * sCb + zh * sCh) : nullptr;

    __shared__ float As[8][128];
    __shared__ float Bs[8][128];

    int tid = threadIdx.x;
    int bn = blockIdx.x * 128, bm = blockIdx.y * 128;
    int arow = tid >> 1, acol = (tid & 1) * 4;
    int tx = tid & 15, ty = tid >> 4;

    float acc[8][8];
    #pragma unroll
    for (int i = 0; i < 8; i++)
        #pragma unroll
        for (int j = 0; j < 8; j++) acc[i][j] = 0.f;

    for (int k0 = 0; k0 < K; k0 += 8) {
        // A tile (transposed into smem)
        float4 av = *(const float4*)(A + (size_t)(bm + arow) * lda + k0 + acol);
        As[acol + 0][arow] = av.x;
        As[acol + 1][arow] = av.y;
        As[acol + 2][arow] = av.z;
        As[acol + 3][arow] = av.w;
        // B tile
        if (TRANSB) {
            int nn = bn + arow;  // same (row, 4col) decomposition
            float4 bv = make_float4(0.f, 0.f, 0.f, 0.f);
            if (nn < N) bv = *(const float4*)(Bm + (size_t)nn * ldb + k0 + acol);
            Bs[acol + 0][arow] = bv.x;
            Bs[acol + 1][arow] = bv.y;
            Bs[acol + 2][arow] = bv.z;
            Bs[acol + 3][arow] = bv.w;
        } else {
            int brow = tid >> 5, bcol = (tid & 31) * 4;
            int nn = bn + bcol;
            float4 bv = make_float4(0.f, 0.f, 0.f, 0.f);
            if (nn < N) bv = *(const float4*)(Bm + (size_t)(k0 + brow) * ldb + nn);
            *(float4*)&Bs[brow][bcol] = bv;
        }
        __syncthreads();
        #pragma unroll
        for (int kk = 0; kk < 8; kk++) {
            float ra[8], rb[8];
            float4 a0 = *(const float4*)&As[kk][ty * 8];
            float4 a1 = *(const float4*)&As[kk][ty * 8 + 4];
            float4 b0 = *(const float4*)&Bs[kk][tx * 8];
            float4 b1 = *(const float4*)&Bs[kk][tx * 8 + 4];
            ra[0]=a0.x; ra[1]=a0.y; ra[2]=a0.z; ra[3]=a0.w;
            ra[4]=a1.x; ra[5]=a1.y; ra[6]=a1.z; ra[7]=a1.w;
            rb[0]=b0.x; rb[1]=b0.y; rb[2]=b0.z; rb[3]=b0.w;
            rb[4]=b1.x; rb[5]=b1.y; rb[6]=b1.z; rb[7]=b1.w;
            #pragma unroll
            for (int i = 0; i < 8; i++)
                #pragma unroll
                for (int j = 0; j < 8; j++)
                    acc[i][j] = fmaf(ra[i], rb[j], acc[i][j]);
        }
        __syncthreads();
    }

    #pragma unroll
    for (int i = 0; i < 8; i++) {
        int row = bm + ty * 8 + i;
        #pragma unroll
        for (int j = 0; j < 8; j++) {
            int col = bn + tx * 8 + j;
            if (col < N) {
                float vv = acc[i][j];
                if (bias) vv += bias[col];
                if (MODE == 1) vv += R0[(size_t)row * ldc + col];
                if (MODE == 2) vv = 0.5f * vv * (1.f + erff(vv * 0.70710678118654752f));
                C[(size_t)row * ldc + col] = vv;
            }
        }
    }
}

// ---------------- host launcher ----------------
static float* symaddr(const void* sym) {
    void* p = nullptr;
    cudaGetSymbolAddress(&p, sym);
    return (float*)p;
}

extern "C" void kernel_launch(void* const* d_in, const int* in_sizes, int n_in,
                              void* d_out, int out_size) {
    const int*   actions      = (const int*)  d_in[0];
    const int*   observations = (const int*)  d_in[1];
    const float* action_emb   = (const float*)d_in[2];
    const float* obs_emb      = (const float*)d_in[3];
    const float* lie_w        = (const float*)d_in[4];
    const float* lie_b        = (const float*)d_in[5];
    const float* Wq  = (const float*)d_in[6];
    const float* bq  = (const float*)d_in[7];
    const float* Wk  = (const float*)d_in[8];
    const float* bk  = (const float*)d_in[9];
    const float* Wv  = (const float*)d_in[10];
    const float* bv  = (const float*)d_in[11];
    const float* Wo  = (const float*)d_in[12];
    const float* bo  = (const float*)d_in[13];
    const float* ln1_g = (const float*)d_in[14];
    const float* ln1_b = (const float*)d_in[15];
    const float* ln2_g = (const float*)d_in[16];
    const float* ln2_b = (const float*)d_in[17];
    const float* w1  = (const float*)d_in[18];
    const float* b1  = (const float*)d_in[19];
    const float* w2  = (const float*)d_in[20];
    const float* b2  = (const float*)d_in[21];
    const float* out_g   = (const float*)d_in[22];
    const float* out_bln = (const float*)d_in[23];
    const float* out_w   = (const float*)d_in[24];
    const float* out_b   = (const float*)d_in[25];
    (void)in_sizes; (void)n_in; (void)out_size;

    float* dlt  = symaddr(g_delta);
    float* cT   = symaddr(g_cos);
    float* sT   = symaddr(g_sin);
    float* x    = symaddr(g_x);
    float* h    = symaddr(g_h);
    float* q    = symaddr(g_q);
    float* k    = symaddr(g_k);
    float* v    = symaddr(g_v);
    float* o    = symaddr(g_o);
    float* ff   = symaddr(g_ff);
    float* sc   = symaddr(g_sc);

    const int BT = Bc * Tc;

    // position state: delta angles -> inclusive cumsum -> cos/sin
    delta_kernel<<<BT, 128>>>(actions, action_emb, lie_w, lie_b, dlt);
    scan_kernel<<<Bc * Rc, Tc>>>(dlt, cT, sT);
    gather_kernel<<<BT, 256>>>(observations, obs_emb, x);

    for (int l = 0; l < Lc; l++) {
        ln_kernel<<<BT, 256>>>(x, ln1_g + l * Dc, ln1_b + l * Dc, h);

        dim3 gQ(Dc / 128, BT / 128, 1);
        gemm_kernel<0,false><<<gQ, 256>>>(h, Wq + (size_t)l*Dc*Dc, bq + l*Dc, nullptr, q,
                                          BT, Dc, Dc, Dc, Dc, Dc, 1, 0,0,0,0,0,0);
        gemm_kernel<0,false><<<gQ, 256>>>(h, Wk + (size_t)l*Dc*Dc, bk + l*Dc, nullptr, k,
                                          BT, Dc, Dc, Dc, Dc, Dc, 1, 0,0,0,0,0,0);
        gemm_kernel<0,false><<<gQ, 256>>>(h, Wv + (size_t)l*Dc*Dc, bv + l*Dc, nullptr, v,
                                          BT, Dc, Dc, Dc, Dc, Dc, 1, 0,0,0,0,0,0);

        rope_kernel<<<(Bc*Tc*Hc*Rc) / 256, 256>>>(cT, sT, q, k);

        // scores[b,h] = Qr (T x 64) * Kr^T -> (T x T)
        dim3 gS(Tc / 128, Tc / 128, Bc * Hc);
        gemm_kernel<0,true><<<gS, 256>>>(q, k, nullptr, nullptr, sc,
                                         Tc, Tc, DHc, Dc, Dc, Tc,
                                         Hc, (long long)Tc*Dc, DHc,
                                             (long long)Tc*Dc, DHc,
                                             (long long)Hc*Tc*Tc, (long long)Tc*Tc);

        softmax_kernel<<<Bc * Hc * Tc, 256>>>(sc);

        // o[b,h] = attn (T x T) * V (T x 64)
        dim3 gA(1, Tc / 128, Bc * Hc);
        gemm_kernel<0,false><<<gA, 256>>>(sc, v, nullptr, nullptr, o,
                                          Tc, DHc, Tc, Tc, Dc, Dc,
                                          Hc, (long long)Hc*Tc*Tc, (long long)Tc*Tc,
                                              (long long)Tc*Dc, DHc,
                                              (long long)Tc*Dc, DHc);

        // x = x + o @ Wo + bo
        gemm_kernel<1,false><<<gQ, 256>>>(o, Wo + (size_t)l*Dc*Dc, bo + l*Dc, x, x,
                                          BT, Dc, Dc, Dc, Dc, Dc, 1, 0,0,0,0,0,0);

        ln_kernel<<<BT, 256>>>(x, ln2_g + l * Dc, ln2_b + l * Dc, h);

        dim3 gF1(FFc / 128, BT / 128, 1);
        gemm_kernel<2,false><<<gF1, 256>>>(h, w1 + (size_t)l*Dc*FFc, b1 + l*FFc, nullptr, ff,
                                           BT, FFc, Dc, Dc, FFc, FFc, 1, 0,0,0,0,0,0);
        dim3 gF2(Dc / 128, BT / 128, 1);
        gemm_kernel<1,false><<<gF2, 256>>>(ff, w2 + (size_t)l*FFc*Dc, b2 + l*Dc, x, x,
                                           BT, Dc, FFc, FFc, Dc, Dc, 1, 0,0,0,0,0,0);
    }

    ln_kernel<<<BT, 256>>>(x, out_g, out_bln, h);
    dim3 gO(OVc / 128, BT / 128, 1);
    gemm_kernel<0,false><<<gO, 256>>>(h, out_w, out_b, nullptr, (float*)d_out,
                                      BT, OVc, Dc, Dc, OVc, OVc, 1, 0,0,0,0,0,0);
}

// round 6
// speedup vs baseline: 1.6906x; 1.6906x over previous
#include <cuda_runtime.h>
#include <cstdint>
#include <cfloat>
#include <math.h>

#define Bc 2
#define Tc 1024
#define Dc 1024
#define Hc 16
#define DHc 64
#define Rc 32
#define Lc 2
#define FFc 4096
#define OVc 16384

// ---------------- static device scratch ----------------
__device__ float g_delta[Bc*Tc*Rc];
__device__ float g_cos[Bc*Tc*Rc];
__device__ float g_sin[Bc*Tc*Rc];
__device__ float g_x [Bc*Tc*Dc];
__device__ float g_h [Bc*Tc*Dc];
__device__ float g_q [Bc*Tc*Dc];
__device__ float g_k [Bc*Tc*Dc];
__device__ float g_v [Bc*Tc*Dc];
__device__ float g_vt[Bc*Hc*DHc*Tc];
__device__ float g_o [Bc*Tc*Dc];
__device__ float g_ff[Bc*Tc*FFc];
__device__ float g_sc[(size_t)Bc*Hc*Tc*Tc];     // 128 MB scores
__device__ float g_wT[40*Dc*Dc];                // transposed weights

#define WT_L(l)   ((size_t)(l) * 12 * Dc * Dc)
#define WT_OUT    ((size_t)24 * Dc * Dc)

// ---------------- helpers ----------------
__device__ __forceinline__ uint32_t smem_u32(const void* p) {
    uint32_t a;
    asm("{ .reg .u64 t; cvta.to.shared.u64 t, %1; cvt.u32.u64 %0, t; }" : "=r"(a) : "l"(p));
    return a;
}
__device__ __forceinline__ float f2tf(float x) {
    uint32_t u; asm("cvt.rna.tf32.f32 %0, %1;" : "=r"(u) : "f"(x));
    return __uint_as_float(u);
}
// split x into tf32 hi + tf32 lo (x ~= hi + lo)
__device__ __forceinline__ void split2(float x, uint32_t& hi, uint32_t& lo) {
    float h = f2tf(x);
    float l = f2tf(x - h);
    hi = __float_as_uint(h);
    lo = __float_as_uint(l);
}
__device__ __forceinline__ void cp16(uint32_t dst, const float* src) {
    asm volatile("cp.async.cg.shared.global [%0], [%1], 16;" :: "r"(dst), "l"(src) : "memory");
}
#define CP_COMMIT() asm volatile("cp.async.commit_group;" ::: "memory")
#define CP_WAIT1()  asm volatile("cp.async.wait_group 1;" ::: "memory")

#define MMA8(d, a, b) \
    asm volatile("mma.sync.aligned.m16n8k8.row.col.f32.tf32.tf32.f32 " \
        "{%0,%1,%2,%3}, {%4,%5,%6,%7}, {%8,%9}, {%0,%1,%2,%3};" \
        : "+f"((d)[0]), "+f"((d)[1]), "+f"((d)[2]), "+f"((d)[3]) \
        : "r"((a)[0]), "r"((a)[1]), "r"((a)[2]), "r"((a)[3]), "r"((b)[0]), "r"((b)[1]))

// ================= 3xTF32 mma.sync GEMM =================
// C[M,N] = A[M,K] * Bt[N,K]^T  (both K-major, raw fp32 inputs)
// 128 x NT tiles, K-chunk 16, double-buffered cp.async pipeline.
// Each fragment element split hi/lo; 3 MMAs per tile recover ~fp32 accuracy.
// MODE 0: +bias(if non-null) | 1: +bias+residual | 2: gelu(+bias)
// CSKIP: skip tiles strictly above diagonal. CKLIM: clamp K at bm+128.
template<int NT, int MODE, bool CSKIP, bool CKLIM>
__global__ void __launch_bounds__(256)
mma_gemm(const float* __restrict__ A, const float* __restrict__ Bt,
         const float* __restrict__ bias, const float* __restrict__ Res,
         float* __restrict__ C,
         int M, int N, int K, int lda, int ldb, int ldc,
         int H2, long long sAb, long long sAh, long long sBb, long long sBh,
         long long sCb, long long sCh)
{
    int bm = blockIdx.y * 128, bn = blockIdx.x * NT;
    if (CSKIP && bn > bm) return;

    int z = blockIdx.z;
    int zb = z / H2, zh = z % H2;
    A  += zb * sAb + zh * sAh;
    Bt += zb * sBb + zh * sBh;
    C  += zb * sCb + zh * sCh;
    const float* R0 = (MODE == 1) ? (Res + zb * sCb + zh * sCh) : nullptr;

    extern __shared__ float sm[];
    const int ASTG = 128 * 20;
    const int BSTG = NT * 20;
    float* Bbase = sm + 2 * ASTG;

    int tid = threadIdx.x;
    int w = tid >> 5, lane = tid & 31;
    int wm = w & 1, wn = w >> 1;              // warp grid 2 x 4
    int g = lane >> 2, tg = lane & 3;
    const int NTILES = NT / 32;

    int Keff = K;
    if (CKLIM) { int kl = bm + 128; Keff = (kl < K) ? kl : K; }
    int NCH = Keff >> 4;

    float acc[4][NTILES][4];
    #pragma unroll
    for (int i = 0; i < 4; i++)
        #pragma unroll
        for (int j = 0; j < NTILES; j++)
            #pragma unroll
            for (int e = 0; e < 4; e++) acc[i][j][e] = 0.f;

    auto copy_chunk = [&](int c, int s) {
        const float* Ak = A + (size_t)bm * lda + c * 16;
        float* As = sm + s * ASTG;
        #pragma unroll
        for (int i = 0; i < 2; i++) {
            int idx = tid + i * 256;
            int row = idx >> 2, seg = idx & 3;
            cp16(smem_u32(As + row * 20 + seg * 4), Ak + (size_t)row * lda + seg * 4);
        }
        const float* Bk = Bt + (size_t)bn * ldb + c * 16;
        float* Bs = Bbase + s * BSTG;
        #pragma unroll
        for (int i = 0; i < NT / 64; i++) {
            int idx = tid + i * 256;
            int row = idx >> 2, seg = idx & 3;
            cp16(smem_u32(Bs + row * 20 + seg * 4), Bk + (size_t)row * ldb + seg * 4);
        }
        CP_COMMIT();
    };

    copy_chunk(0, 0);
    copy_chunk(1, 1);

    for (int c = 0; c < NCH; c++) {
        CP_WAIT1();
        __syncthreads();
        int s = c & 1;
        const float* Ap = sm + s * ASTG;
        const float* Bp = Bbase + s * BSTG;
        #pragma unroll
        for (int ks = 0; ks < 2; ks++) {
            uint32_t ah[4][4], al[4][4];
            #pragma unroll
            for (int mt = 0; mt < 4; mt++) {
                int r0 = wm * 64 + mt * 16 + g;
                split2(Ap[r0 * 20 + ks * 8 + tg],           ah[mt][0], al[mt][0]);
                split2(Ap[(r0 + 8) * 20 + ks * 8 + tg],     ah[mt][1], al[mt][1]);
                split2(Ap[r0 * 20 + ks * 8 + tg + 4],       ah[mt][2], al[mt][2]);
                split2(Ap[(r0 + 8) * 20 + ks * 8 + tg + 4], ah[mt][3], al[mt][3]);
            }
            uint32_t bh[NTILES][2], bl[NTILES][2];
            #pragma unroll
            for (int nt = 0; nt < NTILES; nt++) {
                int n0 = wn * (NT / 4) + nt * 8 + g;
                split2(Bp[n0 * 20 + ks * 8 + tg],     bh[nt][0], bl[nt][0]);
                split2(Bp[n0 * 20 + ks * 8 + tg + 4], bh[nt][1], bl[nt][1]);
            }
            #pragma unroll
            for (int mt = 0; mt < 4; mt++)
                #pragma unroll
                for (int nt = 0; nt < NTILES; nt++) {
                    MMA8(acc[mt][nt], ah[mt], bl[nt]);
                    MMA8(acc[mt][nt], al[mt], bh[nt]);
                    MMA8(acc[mt][nt], ah[mt], bh[nt]);
                }
        }
        __syncthreads();
        if (c + 2 < NCH) copy_chunk(c + 2, s);
    }

    // -------- epilogue --------
    #pragma unroll
    for (int mt = 0; mt < 4; mt++) {
        #pragma unroll
        for (int nt = 0; nt < NTILES; nt++) {
            int row0 = bm + wm * 64 + mt * 16 + g;
            int col  = bn + wn * (NT / 4) + nt * 8 + tg * 2;
            #pragma unroll
            for (int half = 0; half < 2; half++) {
                int row = row0 + half * 8;
                float v0 = acc[mt][nt][half * 2 + 0];
                float v1 = acc[mt][nt][half * 2 + 1];
                if (MODE != 0 || bias) {
                    float2 bv = *(const float2*)(bias + col);
                    v0 += bv.x; v1 += bv.y;
                }
                if (MODE == 1) {
                    float2 rr = *(const float2*)(R0 + (size_t)row * ldc + col);
                    v0 += rr.x; v1 += rr.y;
                }
                if (MODE == 2) {
                    v0 = 0.5f * v0 * (1.f + erff(v0 * 0.70710678118654752f));
                    v1 = 0.5f * v1 * (1.f + erff(v1 * 0.70710678118654752f));
                }
                float2 o = {v0, v1};
                *(float2*)(C + (size_t)row * ldc + col) = o;
            }
        }
    }
}

// ---------------- transpose: in[rows][cols] -> out[cols][rows] ----------------
__global__ void transpose_kernel(const float* __restrict__ in, float* __restrict__ out,
                                 int rows, int cols) {
    __shared__ float tile[32][33];
    int c0 = blockIdx.x * 32, r0 = blockIdx.y * 32;
    int x = threadIdx.x, y = threadIdx.y;
    #pragma unroll
    for (int i = 0; i < 32; i += 8)
        tile[y + i][x] = in[(size_t)(r0 + y + i) * cols + c0 + x];
    __syncthreads();
    #pragma unroll
    for (int i = 0; i < 32; i += 8)
        out[(size_t)(c0 + y + i) * rows + r0 + x] = tile[x][y + i];
}

// v[b][t][h*64+d] -> vt[(b*H+h)*64+d][t]
__global__ void vtrans_kernel(const float* __restrict__ v, float* __restrict__ vt) {
    __shared__ float tile[32][33];
    int z = blockIdx.z, b = z >> 4, h = z & 15;
    int t0 = blockIdx.x * 32, d0 = blockIdx.y * 32;
    int x = threadIdx.x, y = threadIdx.y;
    #pragma unroll
    for (int i = 0; i < 32; i += 8)
        tile[y + i][x] = v[((size_t)(b * Tc + t0 + y + i)) * Dc + h * 64 + d0 + x];
    __syncthreads();
    #pragma unroll
    for (int i = 0; i < 32; i += 8)
        vt[((size_t)z * 64 + d0 + y + i) * Tc + t0 + x] = tile[x][y + i];
}

// ---------------- block reductions ----------------
__device__ __forceinline__ float blockReduceSum(float v) {
    __shared__ float ws[32];
    int lane = threadIdx.x & 31, w = threadIdx.x >> 5;
    #pragma unroll
    for (int o = 16; o; o >>= 1) v += __shfl_down_sync(0xffffffffu, v, o);
    if (lane == 0) ws[w] = v;
    __syncthreads();
    int nw = blockDim.x >> 5;
    v = (threadIdx.x < nw) ? ws[threadIdx.x] : 0.f;
    if (w == 0) {
        #pragma unroll
        for (int o = 16; o; o >>= 1) v += __shfl_down_sync(0xffffffffu, v, o);
        if (lane == 0) ws[0] = v;
    }
    __syncthreads();
    float r = ws[0];
    __syncthreads();
    return r;
}
__device__ __forceinline__ float blockReduceMax(float v) {
    __shared__ float wm[32];
    int lane = threadIdx.x & 31, w = threadIdx.x >> 5;
    #pragma unroll
    for (int o = 16; o; o >>= 1) v = fmaxf(v, __shfl_down_sync(0xffffffffu, v, o));
    if (lane == 0) wm[w] = v;
    __syncthreads();
    int nw = blockDim.x >> 5;
    v = (threadIdx.x < nw) ? wm[threadIdx.x] : -FLT_MAX;
    if (w == 0) {
        #pragma unroll
        for (int o = 16; o; o >>= 1) v = fmaxf(v, __shfl_down_sync(0xffffffffu, v, o));
        if (lane == 0) wm[0] = v;
    }
    __syncthreads();
    float r = wm[0];
    __syncthreads();
    return r;
}

// ---------------- small kernels ----------------
__global__ void delta_kernel(const int* __restrict__ actions,
                             const float* __restrict__ action_emb,
                             const float* __restrict__ lie_w,
                             const float* __restrict__ lie_b,
                             float* __restrict__ delta) {
    int bt = blockIdx.x;
    __shared__ float emb[Dc];
    __shared__ float part[128];
    int a = actions[bt];
    const float* src = action_emb + (size_t)a * Dc;
    for (int i = threadIdx.x; i < Dc; i += blockDim.x) emb[i] = src[i];
    __syncthreads();
    int r = threadIdx.x & 31;
    int seg = threadIdx.x >> 5;
    float s = 0.f;
    int d0 = seg * 256;
    #pragma unroll 8
    for (int d = d0; d < d0 + 256; d++) s += emb[d] * lie_w[d * Rc + r];
    part[threadIdx.x] = s;
    __syncthreads();
    if (threadIdx.x < 32) {
        float v = part[threadIdx.x] + part[threadIdx.x + 32] +
                  part[threadIdx.x + 64] + part[threadIdx.x + 96];
        delta[(size_t)bt * Rc + threadIdx.x] = v + lie_b[threadIdx.x];
    }
}

__global__ void scan_kernel(const float* __restrict__ delta,
                            float* __restrict__ cosT, float* __restrict__ sinT) {
    int b = blockIdx.x / Rc, r = blockIdx.x % Rc;
    __shared__ float buf[2][Tc];
    int t = threadIdx.x;
    buf[0][t] = delta[((size_t)b * Tc + t) * Rc + r];
    __syncthreads();
    int src = 0;
    #pragma unroll
    for (int off = 1; off < Tc; off <<= 1) {
        float nv = buf[src][t];
        if (t >= off) nv += buf[src][t - off];
        buf[1 - src][t] = nv;
        src = 1 - src;
        __syncthreads();
    }
    float th = buf[src][t];
    size_t idx = ((size_t)b * Tc + t) * Rc + r;
    cosT[idx] = cosf(th);
    sinT[idx] = sinf(th);
}

__global__ void gather_kernel(const int* __restrict__ obs,
                              const float* __restrict__ emb,
                              float* __restrict__ x) {
    int bt = blockIdx.x;
    int o = obs[bt];
    const float4* s = (const float4*)(emb + (size_t)o * Dc);
    float4* d = (float4*)(x + (size_t)bt * Dc);
    d[threadIdx.x] = s[threadIdx.x];
}

__global__ void ln_kernel(const float* __restrict__ x,
                          const float* __restrict__ g,
                          const float* __restrict__ b,
                          float* __restrict__ out) {
    int row = blockIdx.x;
    const float4* xr = (const float4*)(x + (size_t)row * Dc);
    float4 v = xr[threadIdx.x];
    float s = v.x + v.y + v.z + v.w;
    s = blockReduceSum(s);
    float mean = s * (1.f / Dc);
    float dx = v.x - mean, dy = v.y - mean, dz = v.z - mean, dw = v.w - mean;
    float s2 = dx*dx + dy*dy + dz*dz + dw*dw;
    s2 = blockReduceSum(s2);
    float rstd = rsqrtf(s2 * (1.f / Dc) + 1e-5f);
    float4 gv = ((const float4*)g)[threadIdx.x];
    float4 bv = ((const float4*)b)[threadIdx.x];
    float4 o;
    o.x = dx * rstd * gv.x + bv.x;
    o.y = dy * rstd * gv.y + bv.y;
    o.z = dz * rstd * gv.z + bv.z;
    o.w = dw * rstd * gv.w + bv.w;
    ((float4*)(out + (size_t)row * Dc))[threadIdx.x] = o;
}

__global__ void rope_kernel(const float* __restrict__ cosT,
                            const float* __restrict__ sinT,
                            float* __restrict__ Q, float* __restrict__ K) {
    int idx = blockIdx.x * blockDim.x + threadIdx.x;
    if (idx >= Bc * Tc * Hc * Rc) return;
    int r = idx & 31;
    int h = (idx >> 5) & 15;
    int bt = idx >> 9;
    float c = cosT[(size_t)bt * Rc + r];
    float s = sinT[(size_t)bt * Rc + r];
    size_t base = (size_t)bt * Dc + h * DHc + 2 * r;
    float2 q = *(float2*)(Q + base);
    float2 k = *(float2*)(K + base);
    float2 qo, ko;
    qo.x = c * q.x - s * q.y;  qo.y = s * q.x + c * q.y;
    ko.x = c * k.x - s * k.y;  ko.y = s * k.x + c * k.y;
    *(float2*)(Q + base) = qo;
    *(float2*)(K + base) = ko;
}

__global__ void softmax_kernel(float* __restrict__ scores) {
    int row = blockIdx.x;
    int t = row & (Tc - 1);
    float* p = scores + (size_t)row * Tc;
    int valid = t + 1;
    float4 v = ((float4*)p)[threadIdx.x];
    int base = threadIdx.x * 4;
    float vals[4] = {v.x, v.y, v.z, v.w};
    float m = -FLT_MAX;
    #pragma unroll
    for (int c = 0; c < 4; c++) {
        vals[c] = (base + c < valid) ? vals[c] * 0.125f : -FLT_MAX;
        m = fmaxf(m, vals[c]);
    }
    m = blockReduceMax(m);
    float s = 0.f;
    #pragma unroll
    for (int c = 0; c < 4; c++) {
        vals[c] = (base + c < valid) ? __expf(vals[c] - m) : 0.f;
        s += vals[c];
    }
    s = blockReduceSum(s);
    float inv = 1.f / s;
    float4 o = {vals[0]*inv, vals[1]*inv, vals[2]*inv, vals[3]*inv};
    ((float4*)p)[threadIdx.x] = o;
}

// ---------------- host launcher ----------------
static float* symaddr(const void* sym) {
    void* p = nullptr;
    cudaGetSymbolAddress(&p, sym);
    return (float*)p;
}

extern "C" void kernel_launch(void* const* d_in, const int* in_sizes, int n_in,
                              void* d_out, int out_size) {
    const int*   actions      = (const int*)  d_in[0];
    const int*   observations = (const int*)  d_in[1];
    const float* action_emb   = (const float*)d_in[2];
    const float* obs_emb      = (const float*)d_in[3];
    const float* lie_w        = (const float*)d_in[4];
    const float* lie_b        = (const float*)d_in[5];
    const float* Wq  = (const float*)d_in[6];
    const float* bq  = (const float*)d_in[7];
    const float* Wk  = (const float*)d_in[8];
    const float* bk  = (const float*)d_in[9];
    const float* Wv  = (const float*)d_in[10];
    const float* bv  = (const float*)d_in[11];
    const float* Wo  = (const float*)d_in[12];
    const float* bo  = (const float*)d_in[13];
    const float* ln1_g = (const float*)d_in[14];
    const float* ln1_b = (const float*)d_in[15];
    const float* ln2_g = (const float*)d_in[16];
    const float* ln2_b = (const float*)d_in[17];
    const float* w1  = (const float*)d_in[18];
    const float* b1  = (const float*)d_in[19];
    const float* w2  = (const float*)d_in[20];
    const float* b2  = (const float*)d_in[21];
    const float* out_g   = (const float*)d_in[22];
    const float* out_bln = (const float*)d_in[23];
    const float* out_w   = (const float*)d_in[24];
    const float* out_b   = (const float*)d_in[25];
    (void)in_sizes; (void)n_in; (void)out_size;

    float* dlt = symaddr(g_delta);
    float* cT  = symaddr(g_cos);
    float* sT  = symaddr(g_sin);
    float* x   = symaddr(g_x);
    float* h   = symaddr(g_h);
    float* q   = symaddr(g_q);
    float* k   = symaddr(g_k);
    float* v   = symaddr(g_v);
    float* vt  = symaddr(g_vt);
    float* o   = symaddr(g_o);
    float* ff  = symaddr(g_ff);
    float* sc  = symaddr(g_sc);
    float* wT  = symaddr(g_wT);

    const int BT = Bc * Tc;
    const int SM128 = (2 * 128 * 20 + 2 * 128 * 20) * 4;   // 40960
    const int SM64  = (2 * 128 * 20 + 2 * 64 * 20) * 4;    // 30720

    dim3 tb(32, 8);
    for (int l = 0; l < Lc; l++) {
        size_t base = WT_L(l);
        transpose_kernel<<<dim3(32, 32), tb>>>(Wq + (size_t)l*Dc*Dc, wT + base + 0*Dc*Dc, Dc, Dc);
        transpose_kernel<<<dim3(32, 32), tb>>>(Wk + (size_t)l*Dc*Dc, wT + base + 1*Dc*Dc, Dc, Dc);
        transpose_kernel<<<dim3(32, 32), tb>>>(Wv + (size_t)l*Dc*Dc, wT + base + 2*Dc*Dc, Dc, Dc);
        transpose_kernel<<<dim3(32, 32), tb>>>(Wo + (size_t)l*Dc*Dc, wT + base + 3*Dc*Dc, Dc, Dc);
        transpose_kernel<<<dim3(128,32), tb>>>(w1 + (size_t)l*Dc*FFc, wT + base + 4*(size_t)Dc*Dc, Dc, FFc);
        transpose_kernel<<<dim3(32,128), tb>>>(w2 + (size_t)l*FFc*Dc, wT + base + 8*(size_t)Dc*Dc, FFc, Dc);
    }
    transpose_kernel<<<dim3(512, 32), tb>>>(out_w, wT + WT_OUT, Dc, OVc);

    delta_kernel<<<BT, 128>>>(actions, action_emb, lie_w, lie_b, dlt);
    scan_kernel<<<Bc * Rc, Tc>>>(dlt, cT, sT);
    gather_kernel<<<BT, 256>>>(observations, obs_emb, x);

    for (int l = 0; l < Lc; l++) {
        size_t wb = WT_L(l);
        ln_kernel<<<BT, 256>>>(x, ln1_g + l * Dc, ln1_b + l * Dc, h);

        dim3 gQ(Dc / 128, BT / 128, 1);
        mma_gemm<128,0,false,false><<<gQ, 256, SM128>>>(h, wT + wb + 0*Dc*Dc, bq + l*Dc, nullptr, q,
            BT, Dc, Dc, Dc, Dc, Dc, 1, 0,0,0,0,0,0);
        mma_gemm<128,0,false,false><<<gQ, 256, SM128>>>(h, wT + wb + 1*Dc*Dc, bk + l*Dc, nullptr, k,
            BT, Dc, Dc, Dc, Dc, Dc, 1, 0,0,0,0,0,0);
        mma_gemm<128,0,false,false><<<gQ, 256, SM128>>>(h, wT + wb + 2*Dc*Dc, bv + l*Dc, nullptr, v,
            BT, Dc, Dc, Dc, Dc, Dc, 1, 0,0,0,0,0,0);

        rope_kernel<<<(Bc*Tc*Hc*Rc) / 256, 256>>>(cT, sT, q, k);
        vtrans_kernel<<<dim3(32, 2, 32), tb>>>(v, vt);

        // scores = Qr @ Kr^T (causal tiles only)
        dim3 gS(Tc / 128, Tc / 128, Bc * Hc);
        mma_gemm<128,0,true,false><<<gS, 256, SM128>>>(q, k, nullptr, nullptr, sc,
            Tc, Tc, DHc, Dc, Dc, Tc,
            Hc, (long long)Tc*Dc, DHc, (long long)Tc*Dc, DHc,
                (long long)Hc*Tc*Tc, (long long)Tc*Tc);

        softmax_kernel<<<Bc * Hc * Tc, 256>>>(sc);

        // o = attn @ V (K clamped to diagonal)
        dim3 gA(1, Tc / 128, Bc * Hc);
        mma_gemm<64,0,false,true><<<gA, 256, SM64>>>(sc, vt, nullptr, nullptr, o,
            Tc, DHc, Tc, Tc, Tc, Dc,
            Hc, (long long)Hc*Tc*Tc, (long long)Tc*Tc,
                (long long)Hc*DHc*Tc, (long long)DHc*Tc,
                (long long)Tc*Dc, (long long)DHc);

        // x = x + o @ Wo + bo
        mma_gemm<128,1,false,false><<<gQ, 256, SM128>>>(o, wT + wb + 3*Dc*Dc, bo + l*Dc, x, x,
            BT, Dc, Dc, Dc, Dc, Dc, 1, 0,0,0,0,0,0);

        ln_kernel<<<BT, 256>>>(x, ln2_g + l * Dc, ln2_b + l * Dc, h);

        dim3 gF1(FFc / 128, BT / 128, 1);
        mma_gemm<128,2,false,false><<<gF1, 256, SM128>>>(h, wT + wb + 4*(size_t)Dc*Dc, b1 + l*FFc, nullptr, ff,
            BT, FFc, Dc, Dc, Dc, FFc, 1, 0,0,0,0,0,0);
        dim3 gF2(Dc / 128, BT / 128, 1);
        mma_gemm<128,1,false,false><<<gF2, 256, SM128>>>(ff, wT + wb + 8*(size_t)Dc*Dc, b2 + l*Dc, x, x,
            BT, Dc, FFc, FFc, FFc, Dc, 1, 0,0,0,0,0,0);
    }

    ln_kernel<<<BT, 256>>>(x, out_g, out_bln, h);
    dim3 gO(OVc / 128, BT / 128, 1);
    mma_gemm<128,0,false,false><<<gO, 256, SM128>>>(h, wT + WT_OUT, out_b, nullptr, (float*)d_out,
        BT, OVc, Dc, Dc, Dc, OVc, 1, 0,0,0,0,0,0);
}